// round 12
// baseline (speedup 1.0000x reference)
#include <cuda_runtime.h>
#include <math.h>
#include <cstdint>

#define BATCH 4
#define SEQ   8192
#define DIM   512

// ---- Kernel 1: 128x256 tiles, K-split 4, fp16 m16n8k16, ldmatrix frags ----
#define TM    128
#define TN    256
#define TK    16              // K per chunk
#define SPLITS 4
#define KSPLIT (SEQ/SPLITS)
#define NITER (KSPLIT/TK)     // 128 chunks, 64 bodies
#define NBUF  4
#define AROWB 272             // bytes per A k-row (128 f16 + pad)
#define BROWB 528             // bytes per B k-row (256 f16 + pad)
#define CH_A  (16*AROWB)      // 4352 B
#define CH_BB (16*BROWB)      // 8448 B
#define CHB   (CH_A + CH_BB)  // 12800 B per chunk
#define K1_SMEM (NBUF*CHB)    // 51200 B (dynamic)

// ---- Kernel 2: 32x64 tiles, warp tile 16x16 ----
#define TM2   32
#define TN2   64
#define TK2   16
#define NIT2  (DIM/TK2)
#define AR2   12
#define BR2   72

__device__ float    g_P[(size_t)SPLITS*BATCH*DIM*DIM];   // 16 MB f32 split partials
__device__ unsigned g_Mh[(size_t)BATCH*(DIM/2)*DIM];     // 4 MB f16x2-packed M
__device__ float    g_V[SPLITS*BATCH*DIM];
__device__ float    g_v[BATCH*DIM];

__device__ __forceinline__ unsigned pkh(float lo, float hi){
    unsigned u; asm("cvt.rn.f16x2.f32 %0, %1, %2;" : "=r"(u) : "f"(hi), "f"(lo)); return u;
}
__device__ __forceinline__ void mma_f16(float c[4], const unsigned a[4], unsigned b0, unsigned b1){
    asm("mma.sync.aligned.m16n8k16.row.col.f32.f16.f16.f32 "
        "{%0,%1,%2,%3},{%4,%5,%6,%7},{%8,%9},{%0,%1,%2,%3};"
        : "+f"(c[0]), "+f"(c[1]), "+f"(c[2]), "+f"(c[3])
        : "r"(a[0]), "r"(a[1]), "r"(a[2]), "r"(a[3]), "r"(b0), "r"(b1));
}
__device__ __forceinline__ unsigned su32(const void* p){
    unsigned r;
    asm("{ .reg .u64 t; cvta.to.shared.u64 t, %1; cvt.u32.u64 %0, t; }" : "=r"(r) : "l"(p));
    return r;
}
#define LDSM4T(r, addr) \
    asm volatile("ldmatrix.sync.aligned.m8n8.x4.trans.shared.b16 {%0,%1,%2,%3}, [%4];" \
        : "=r"((r)[0]), "=r"((r)[1]), "=r"((r)[2]), "=r"((r)[3]) : "r"(addr))
#define STSV2(addr, u0, u1) \
    asm volatile("st.shared.v2.b32 [%0], {%1, %2};" :: "r"(addr), "r"(u0), "r"(u1))

// ---------------------------------------------------------------------------
// Kernel 1: g_P[split,b][mt*128+m][nt*256+n] = sum_t w_t H[t,m'] E[t,n']
//           g_V (mt==0 CTAs). Warp tile 64x64 (2x4 warp grid), 1 CTA/SM.
// ---------------------------------------------------------------------------
__global__ void __launch_bounds__(256,1)
k1_outer(const float* __restrict__ H, const float* __restrict__ E)
{
    extern __shared__ __align__(16) unsigned char sbuf[];

    const int tid  = threadIdx.x;
    const int lane = tid & 31;
    const int warp = tid >> 5;
    const int wm = warp & 1, wn = warp >> 1;   // 2m x 4n grid, warp tile 64x64
    const int tg = lane & 3;
    const int gp = lane >> 2;

    const int x     = blockIdx.x;
    const int split = x & 3;
    const int nt    = (x >> 2) & 1;
    const int mt    = (x >> 3) & 3;
    const int b     = x >> 5;
    const int k0    = split * KSPLIT;

    const unsigned sb = su32(sbuf);

    // ---- consumer fragment lane offsets ----
    const unsigned klA = (unsigned)((lane & 7) + ((lane >= 16) ? 8 : 0));
    const unsigned offA = klA*AROWB + (unsigned)(((lane >> 3) & 1) * 16) + (unsigned)(wm*128);
    const unsigned klB = (unsigned)((lane & 7) + (((lane >> 3) & 1) ? 8 : 0));
    const unsigned offB = klB*BROWB + (unsigned)((lane >= 16) ? 16 : 0) + (unsigned)(wn*128);

    // ---- producer coords: rows kr, kr+8; A 1 col-pair, B 2 col-pairs ----
    const int kr = tid >> 5;
    const int c4 = tid & 31;
    const float* Ap = H + ((size_t)(b*SEQ + k0 + kr))*DIM + mt*TM + 4*c4;
    const float* Bp = E + ((size_t)(b*SEQ + k0 + kr))*DIM + nt*TN + 4*c4;
    const size_t step = (size_t)TK*DIM;

    const float lnalpha = logf((float)0.9996165783279395);
    const float c8f  = expf(-8.0f*lnalpha);
    const float c16f = expf(-16.0f*lnalpha);
    float wt = expf((float)(SEQ-1 - (k0 + kr)) * lnalpha);

    float acc[4][8][4];
    #pragma unroll
    for (int i=0;i<4;i++)
        #pragma unroll
        for (int j=0;j<8;j++)
            #pragma unroll
            for (int r=0;r<4;r++) acc[i][j][r]=0.f;

    const bool dov = (mt == 0);
    float vacc[8];
    #pragma unroll
    for (int i=0;i<8;i++) vacc[i]=0.f;

    // q layout: [0]=A kr, [1]=A kr+8, [2]=B kr c4, [3]=B kr c4+32,
    //           [4]=B kr+8 c4, [5]=B kr+8 c4+32
    float4 q0[6], q1[6];

    auto ldq = [&](int ck, float4* q){
        const float* ap = Ap + (size_t)ck*step;
        const float* bp = Bp + (size_t)ck*step;
        q[0] = *(const float4*)(ap);
        q[1] = *(const float4*)(ap + 8*DIM);
        q[2] = *(const float4*)(bp);
        q[3] = *(const float4*)(bp + 128);
        q[4] = *(const float4*)(bp + 8*DIM);
        q[5] = *(const float4*)(bp + 8*DIM + 128);
    };
    auto stq = [&](int buf, const float4* q){
        const unsigned baseA = sb + (unsigned)(buf*CHB) + (unsigned)(kr*AROWB) + (unsigned)(c4*8);
        const unsigned baseB = sb + (unsigned)(buf*CHB) + CH_A + (unsigned)(kr*BROWB) + (unsigned)(c4*8);
        STSV2(baseA,           pkh(q[0].x,q[0].y), pkh(q[0].z,q[0].w));
        STSV2(baseA + 8*AROWB, pkh(q[1].x,q[1].y), pkh(q[1].z,q[1].w));
        const float w0 = wt, w1 = wt*c8f;
        float a0=q[2].x*w0, a1=q[2].y*w0, a2=q[2].z*w0, a3=q[2].w*w0;
        float b0=q[3].x*w0, b1=q[3].y*w0, b2=q[3].z*w0, b3=q[3].w*w0;
        float c0=q[4].x*w1, c1=q[4].y*w1, c2=q[4].z*w1, c3=q[4].w*w1;
        float d0=q[5].x*w1, d1=q[5].y*w1, d2=q[5].z*w1, d3=q[5].w*w1;
        if (dov){
            vacc[0]+=a0+c0; vacc[1]+=a1+c1; vacc[2]+=a2+c2; vacc[3]+=a3+c3;
            vacc[4]+=b0+d0; vacc[5]+=b1+d1; vacc[6]+=b2+d2; vacc[7]+=b3+d3;
        }
        STSV2(baseB,                 pkh(a0,a1), pkh(a2,a3));
        STSV2(baseB + 256,           pkh(b0,b1), pkh(b2,b3));
        STSV2(baseB + 8*BROWB,       pkh(c0,c1), pkh(c2,c3));
        STSV2(baseB + 8*BROWB + 256, pkh(d0,d1), pkh(d2,d3));
        wt *= c16f;
    };
    auto do_mma = [&](int buf){
        const unsigned Ab = sb + (unsigned)(buf*CHB);
        const unsigned Bb = Ab + CH_A;
        unsigned a[4][4], bf[4][4];
        #pragma unroll
        for (int i=0;i<4;i++) LDSM4T(a[i],  Ab + offA + (unsigned)(32*i));
        #pragma unroll
        for (int j=0;j<4;j++) LDSM4T(bf[j], Bb + offB + (unsigned)(32*j));
        #pragma unroll
        for (int i=0;i<4;i++){
            #pragma unroll
            for (int j=0;j<4;j++){
                mma_f16(acc[i][2*j],   a[i], bf[j][0], bf[j][1]);
                mma_f16(acc[i][2*j+1], a[i], bf[j][2], bf[j][3]);
            }
        }
    };

    // prologue: buffers 0,1 <- chunks 0,1; q0,q1 <- chunks 2,3
    ldq(0, q0); ldq(1, q1);
    stq(0, q0); stq(1, q1);
    ldq(2, q0); ldq(3, q1);
    __syncthreads();

    #pragma unroll 1
    for (int it = 0; it < NITER; it += 2){
        if (it + 2 < NITER){
            stq((it+2)&3, q0);
            stq((it+3)&3, q1);
        }
        if (it + 4 < NITER){
            ldq(it+4, q0);
            ldq(it+5, q1);
        }
        do_mma(it & 3);
        do_mma((it+1) & 3);
        __syncthreads();
    }

    // write f32 partial tile (128x256)
    float* Pp = g_P + (((size_t)(split*BATCH + b))*DIM + mt*TM)*DIM + nt*TN;
    #pragma unroll
    for (int i=0;i<4;i++){
        const int r = 64*wm + 16*i + gp;
        #pragma unroll
        for (int j=0;j<8;j++){
            const int cc = 64*wn + 8*j + 2*tg;
            *(float2*)&Pp[(size_t)r*DIM + cc]     = make_float2(acc[i][j][0], acc[i][j][1]);
            *(float2*)&Pp[(size_t)(r+8)*DIM + cc] = make_float2(acc[i][j][2], acc[i][j][3]);
        }
    }

    // v partial: reduce over kr groups (sbuf is free after last loop barrier)
    if (dov){
        float* vsm = (float*)sbuf;
        #pragma unroll
        for (int i=0;i<8;i++) vsm[tid*8 + i] = vacc[i];
        __syncthreads();
        if (tid < 32){
            float s[8];
            #pragma unroll
            for (int i=0;i<8;i++) s[i]=0.f;
            #pragma unroll
            for (int r=0;r<8;r++){
                const float* p = vsm + ((r<<5) + tid)*8;
                #pragma unroll
                for (int i=0;i<8;i++) s[i] += p[i];
            }
            float* vp = g_V + ((size_t)split*BATCH + b)*DIM + nt*TN;
            *(float4*)&vp[4*tid]       = make_float4(s[0],s[1],s[2],s[3]);
            *(float4*)&vp[128 + 4*tid] = make_float4(s[4],s[5],s[6],s[7]);
        }
    }
}

// ---------------------------------------------------------------------------
// Reduction: g_Mh[b][kp][d] = pack_f16x2(sum_p P[2kp][d], sum_p P[2kp+1][d]);
//            g_v = sum_p g_V
// ---------------------------------------------------------------------------
__global__ void __launch_bounds__(256)
kred()
{
    const int gid = blockIdx.x*blockDim.x + threadIdx.x;
    const int d4 = gid & 127;
    const int kp = (gid >> 7) & 255;
    const int b  = gid >> 15;

    const size_t pstride = (size_t)BATCH*DIM*DIM;
    const float* base = g_P + ((size_t)b*DIM + 2*kp)*DIM + 4*d4;
    float4 s0 = *(const float4*)(base);
    float4 s1 = *(const float4*)(base + DIM);
    #pragma unroll
    for (int p=1;p<SPLITS;p++){
        float4 t0 = *(const float4*)(base + p*pstride);
        float4 t1 = *(const float4*)(base + p*pstride + DIM);
        s0.x+=t0.x; s0.y+=t0.y; s0.z+=t0.z; s0.w+=t0.w;
        s1.x+=t1.x; s1.y+=t1.y; s1.z+=t1.z; s1.w+=t1.w;
    }
    uint4 u;
    u.x = pkh(s0.x, s1.x);
    u.y = pkh(s0.y, s1.y);
    u.z = pkh(s0.z, s1.z);
    u.w = pkh(s0.w, s1.w);
    ((uint4*)g_Mh)[((size_t)b*256 + kp)*128 + d4] = u;

    if (gid < BATCH*DIM/4){
        const float4* Vin = (const float4*)g_V;
        float4 s = Vin[gid];
        #pragma unroll
        for (int p=1;p<SPLITS;p++){
            float4 t = Vin[gid + p*(BATCH*DIM/4)];
            s.x+=t.x; s.y+=t.y; s.z+=t.z; s.w+=t.w;
        }
        ((float4*)g_v)[gid] = s;
    }
}

// ---------------------------------------------------------------------------
// Kernel 2: C[b,s,d] = sum_d' W[s,d'] * M[b,d',d] + bias[s]*v[b,d]
// 32x64 tiles, warp tile 16x16, grid 512 for occupancy.
// ---------------------------------------------------------------------------
__global__ void __launch_bounds__(256,4)
k2_proj(const float* __restrict__ Wm, const float* __restrict__ bias, float* __restrict__ out)
{
    __shared__ unsigned Ah[2][TM2][AR2];
    __shared__ unsigned Bh[2][8][BR2];

    const int tid  = threadIdx.x;
    const int lane = tid & 31;
    const int warp = tid >> 5;
    const int wm = warp & 1, wn = warp >> 1;
    const int tg = lane & 3;
    const int gp = lane >> 2;

    const int x  = blockIdx.x;
    const int nt = x & 7;
    const int mt = (x >> 3) & 15;
    const int b  = x >> 7;

    const bool ldA = (tid < 128);
    const int am  = tid >> 2;
    const int ak4 = tid & 3;
    const int pt  = tid - 128;
    const int bk  = pt >> 4;
    const int bn4 = pt & 15;

    const float* Wp = Wm + (size_t)(mt*TM2 + am)*DIM + 4*ak4;
    const unsigned* Mp = g_Mh + ((size_t)b*256 + bk)*512 + nt*TN2 + 4*bn4;

    float acc[2][4];
    #pragma unroll
    for (int j=0;j<2;j++)
        #pragma unroll
        for (int r=0;r<4;r++) acc[j][r]=0.f;

    float4 wq0, wq1; uint4 mq0, mq1;

    auto ldq = [&](int it, float4& wq, uint4& mq){
        if (ldA) wq = *(const float4*)(Wp + it*TK2);
        else     mq = *(const uint4*)(Mp + (size_t)it*8*512);
    };
    auto stq = [&](int buf, const float4& wq, const uint4& mq){
        if (ldA){
            Ah[buf][am][2*ak4]   = pkh(wq.x, wq.y);
            Ah[buf][am][2*ak4+1] = pkh(wq.z, wq.w);
        } else {
            *(uint4*)&Bh[buf][bk][4*bn4] = mq;
        }
    };
    auto do_mma = [&](int buf){
        unsigned a[4];
        const int mb = 16*wm + gp;
        a[0] = Ah[buf][mb][tg];
        a[1] = Ah[buf][mb+8][tg];
        a[2] = Ah[buf][mb][tg+4];
        a[3] = Ah[buf][mb+8][tg+4];
        const unsigned* Br0 = Bh[buf][tg];
        const unsigned* Br4 = Bh[buf][tg+4];
        #pragma unroll
        for (int j=0;j<2;j++){
            const int nb = 16*wn + 8*j + gp;
            unsigned b0 = Br0[nb];
            unsigned b1 = Br4[nb];
            mma_f16(acc[j], a, b0, b1);
        }
    };

    ldq(0, wq0, mq0);
    stq(0, wq0, mq0);
    ldq(1, wq1, mq1);
    __syncthreads();

    #pragma unroll 1
    for (int it = 0; it < NIT2; it += 2){
        if (it + 2 < NIT2) ldq(it + 2, wq0, mq0);
        if (it + 1 < NIT2) stq(1, wq1, mq1);
        do_mma(0);
        __syncthreads();
        if (it + 3 < NIT2) ldq(it + 3, wq1, mq1);
        if (it + 2 < NIT2) stq(0, wq0, mq0);
        do_mma(1);
        __syncthreads();
    }

    float* Co = out + (((size_t)b)*DIM + mt*TM2)*DIM + nt*TN2;
    const int r0 = 16*wm + gp;
    const float b0s = bias[mt*TM2 + r0];
    const float b1s = bias[mt*TM2 + r0 + 8];
    #pragma unroll
    for (int j=0;j<2;j++){
        const int cc = 16*wn + 8*j + 2*tg;
        const float* vp = g_v + (size_t)b*DIM + nt*TN2 + cc;
        float v0 = vp[0], v1 = vp[1];
        *(float2*)&Co[(size_t)r0*DIM + cc] =
            make_float2(acc[j][0] + b0s*v0, acc[j][1] + b0s*v1);
        *(float2*)&Co[(size_t)(r0+8)*DIM + cc] =
            make_float2(acc[j][2] + b1s*v0, acc[j][3] + b1s*v1);
    }
}

extern "C" void kernel_launch(void* const* d_in, const int* in_sizes, int n_in,
                              void* d_out, int out_size)
{
    const float* H    = (const float*)d_in[0];   // hidden_states (4,8192,512)
    const float* E    = (const float*)d_in[1];   // positional_encodings (4,8192,512)
    const float* Wm   = (const float*)d_in[2];   // W (512,512)
    const float* bias = (const float*)d_in[3];   // b (512,)
    float* out = (float*)d_out;                  // (4,512,512)

    cudaFuncSetAttribute(k1_outer, cudaFuncAttributeMaxDynamicSharedMemorySize, K1_SMEM);

    k1_outer<<<BATCH*4*2*SPLITS, 256, K1_SMEM>>>(H, E);
    kred<<<512, 256>>>();
    k2_proj<<<BATCH*16*8, 256>>>(Wm, bias, out);
}

// round 13
// speedup vs baseline: 1.0608x; 1.0608x over previous
#include <cuda_runtime.h>
#include <math.h>
#include <cstdint>

#define BATCH 4
#define SEQ   8192
#define DIM   512

// ---- Kernel 1: 128x128 tiles, K-split 4, fp16 m16n8k16, ldmatrix frags ----
#define TM    128
#define TN    128
#define TK    16              // K per chunk
#define SPLITS 4
#define KSPLIT (SEQ/SPLITS)
#define NITER (KSPLIT/TK)     // 128 chunks, 64 bodies
#define NBUF  4
#define AROWB 272             // bytes per k-row (128 f16 + 8 f16 pad)
#define CH_A  (16*AROWB)      // 4352 B per operand chunk
#define CH_B  (2*CH_A)        // 8704 B per chunk (A+B)

// ---- Kernel 2: 32x64 tiles, warp tile 16x16, 4-buffer / 2-chunk bodies ----
#define TM2   32
#define TN2   64
#define TK2   16
#define NIT2  (DIM/TK2)       // 32
#define AR2   12
#define BR2   72

__device__ float    g_P[(size_t)SPLITS*BATCH*DIM*DIM];   // 16 MB f32 split partials
__device__ unsigned g_Mh[(size_t)BATCH*(DIM/2)*DIM];     // 4 MB f16x2-packed M
__device__ float    g_V[SPLITS*BATCH*DIM];
__device__ float    g_v[BATCH*DIM];

__device__ __forceinline__ unsigned pkh(float lo, float hi){
    unsigned u; asm("cvt.rn.f16x2.f32 %0, %1, %2;" : "=r"(u) : "f"(hi), "f"(lo)); return u;
}
__device__ __forceinline__ void mma_f16(float c[4], const unsigned a[4], unsigned b0, unsigned b1){
    asm("mma.sync.aligned.m16n8k16.row.col.f32.f16.f16.f32 "
        "{%0,%1,%2,%3},{%4,%5,%6,%7},{%8,%9},{%0,%1,%2,%3};"
        : "+f"(c[0]), "+f"(c[1]), "+f"(c[2]), "+f"(c[3])
        : "r"(a[0]), "r"(a[1]), "r"(a[2]), "r"(a[3]), "r"(b0), "r"(b1));
}
__device__ __forceinline__ unsigned su32(const void* p){
    unsigned r;
    asm("{ .reg .u64 t; cvta.to.shared.u64 t, %1; cvt.u32.u64 %0, t; }" : "=r"(r) : "l"(p));
    return r;
}
#define LDSM4T(r, addr) \
    asm volatile("ldmatrix.sync.aligned.m8n8.x4.trans.shared.b16 {%0,%1,%2,%3}, [%4];" \
        : "=r"((r)[0]), "=r"((r)[1]), "=r"((r)[2]), "=r"((r)[3]) : "r"(addr))
#define STSV2(addr, u0, u1) \
    asm volatile("st.shared.v2.b32 [%0], {%1, %2};" :: "r"(addr), "r"(u0), "r"(u1))

// ---------------------------------------------------------------------------
// Kernel 1: g_P[split,b][m][n] = sum_t w_t H[t,m] E[t,n]
//           g_V: every CTA covers its disjoint 32-column slice (balanced)
// ---------------------------------------------------------------------------
__global__ void __launch_bounds__(256,2)
k1_outer(const float* __restrict__ H, const float* __restrict__ E)
{
    __shared__ __align__(16) unsigned char sbuf[NBUF*CH_B];   // 34816 B
    __shared__ float vsm[256*4];

    const int tid  = threadIdx.x;
    const int lane = tid & 31;
    const int warp = tid >> 5;
    const int wm = warp & 3, wn = warp >> 2;   // warp tile 32m x 64n
    const int tg = lane & 3;
    const int gp = lane >> 2;

    const int x     = blockIdx.x;
    const int split = x & 3;
    const int nt    = (x >> 2) & 3;
    const int mt    = (x >> 4) & 3;
    const int b     = x >> 6;
    const int k0    = split * KSPLIT;

    const unsigned sb = su32(sbuf);

    // ---- consumer fragment lane offsets (bytes within chunk) ----
    const unsigned klA = (unsigned)((lane & 7) + ((lane >= 16) ? 8 : 0));
    const unsigned offA = klA*AROWB + (unsigned)(((lane >> 3) & 1) * 16) + (unsigned)(32*wm*2);
    const unsigned klB = (unsigned)((lane & 7) + (((lane >> 3) & 1) ? 8 : 0));
    const unsigned offB = klB*AROWB + (unsigned)((lane >= 16) ? 16 : 0) + (unsigned)(64*wn*2);

    // ---- producer coords ----
    const int kr = tid >> 5;   // k row 0..7 (also handles kr+8)
    const int c4 = tid & 31;   // float4 column
    const float* Ap = H + ((size_t)(b*SEQ + k0 + kr))*DIM + mt*TM + 4*c4;
    const float* Bp = E + ((size_t)(b*SEQ + k0 + kr))*DIM + nt*TN + 4*c4;
    const size_t step = (size_t)TK*DIM;

    const float lnalpha = logf((float)0.9996165783279395);
    const float c8f  = expf(-8.0f*lnalpha);
    const float c16f = expf(-16.0f*lnalpha);
    float wt = expf((float)(SEQ-1 - (k0 + kr)) * lnalpha);

    float acc[2][8][4];
    #pragma unroll
    for (int i=0;i<2;i++)
        #pragma unroll
        for (int j=0;j<8;j++)
            #pragma unroll
            for (int r=0;r<4;r++) acc[i][j][r]=0.f;

    // balanced v: this thread contributes iff its columns fall in this CTA's slice
    const bool dovt = ((c4 >> 3) == mt);
    float vacc[4] = {0.f,0.f,0.f,0.f};

    float4 q0[4], q1[4];     // [A row kr, A row kr+8, B row kr, B row kr+8]

    auto ldq = [&](int ck, float4* q){
        const float* ap = Ap + (size_t)ck*step;
        const float* bp = Bp + (size_t)ck*step;
        q[0] = *(const float4*)(ap);
        q[1] = *(const float4*)(ap + 8*DIM);
        q[2] = *(const float4*)(bp);
        q[3] = *(const float4*)(bp + 8*DIM);
    };
    auto stq = [&](int buf, const float4* q){
        unsigned base = sb + (unsigned)(buf*CH_B) + (unsigned)(kr*AROWB) + (unsigned)(c4*8);
        STSV2(base,           pkh(q[0].x,q[0].y), pkh(q[0].z,q[0].w));
        STSV2(base + 8*AROWB, pkh(q[1].x,q[1].y), pkh(q[1].z,q[1].w));
        const float w0 = wt, w1 = wt*c8f;
        float s0x=q[2].x*w0, s0y=q[2].y*w0, s0z=q[2].z*w0, s0w=q[2].w*w0;
        float s1x=q[3].x*w1, s1y=q[3].y*w1, s1z=q[3].z*w1, s1w=q[3].w*w1;
        if (dovt){ vacc[0]+=s0x+s1x; vacc[1]+=s0y+s1y; vacc[2]+=s0z+s1z; vacc[3]+=s0w+s1w; }
        STSV2(base + CH_A,           pkh(s0x,s0y), pkh(s0z,s0w));
        STSV2(base + CH_A + 8*AROWB, pkh(s1x,s1y), pkh(s1z,s1w));
        wt *= c16f;
    };
    auto do_mma = [&](int buf){
        const unsigned Ab = sb + (unsigned)(buf*CH_B);
        const unsigned Bb = Ab + CH_A;
        unsigned a[2][4];
        LDSM4T(a[0], Ab + offA);
        LDSM4T(a[1], Ab + offA + 32);
        unsigned bf[4][4];
        #pragma unroll
        for (int jj=0;jj<4;jj++) LDSM4T(bf[jj], Bb + offB + (unsigned)(jj*32));
        #pragma unroll
        for (int i=0;i<2;i++){
            #pragma unroll
            for (int jj=0;jj<4;jj++){
                mma_f16(acc[i][2*jj],   a[i], bf[jj][0], bf[jj][1]);
                mma_f16(acc[i][2*jj+1], a[i], bf[jj][2], bf[jj][3]);
            }
        }
    };

    // prologue: buffers 0,1 <- chunks 0,1; q0,q1 <- chunks 2,3
    ldq(0, q0); ldq(1, q1);
    stq(0, q0); stq(1, q1);
    ldq(2, q0); ldq(3, q1);
    __syncthreads();

    #pragma unroll 1
    for (int it = 0; it < NITER; it += 2){
        // consume buffers it&3, (it+1)&3; fill (it+2)&3, (it+3)&3
        do_mma(it & 3);
        if (it + 2 < NITER){
            stq((it+2)&3, q0);
            stq((it+3)&3, q1);
        }
        if (it + 4 < NITER){
            ldq(it+4, q0);
            ldq(it+5, q1);
        }
        do_mma((it+1) & 3);
        __syncthreads();
    }

    // write f32 partial tile
    float* Pp = g_P + (((size_t)(split*BATCH + b))*DIM + mt*TM)*DIM + nt*TN;
    #pragma unroll
    for (int i=0;i<2;i++){
        const int r = 32*wm + 16*i + gp;
        #pragma unroll
        for (int j=0;j<8;j++){
            const int cc = 64*wn + 8*j + 2*tg;
            *(float2*)&Pp[(size_t)r*DIM + cc]     = make_float2(acc[i][j][0], acc[i][j][1]);
            *(float2*)&Pp[(size_t)(r+8)*DIM + cc] = make_float2(acc[i][j][2], acc[i][j][3]);
        }
    }

    // balanced v reduction: this CTA owns cols [nt*128 + mt*32, +32)
    vsm[tid*4+0]=vacc[0]; vsm[tid*4+1]=vacc[1]; vsm[tid*4+2]=vacc[2]; vsm[tid*4+3]=vacc[3];
    __syncthreads();
    if (tid < 8){
        const int cm = 8*mt + tid;            // matching c4 value
        float s0=0.f,s1=0.f,s2=0.f,s3=0.f;
        #pragma unroll
        for (int r=0;r<8;r++){
            const float* p = vsm + ((r<<5) + cm)*4;
            s0+=p[0]; s1+=p[1]; s2+=p[2]; s3+=p[3];
        }
        float* vp = g_V + ((size_t)split*BATCH + b)*DIM + nt*TN + mt*32 + 4*tid;
        vp[0]=s0; vp[1]=s1; vp[2]=s2; vp[3]=s3;
    }
}

// ---------------------------------------------------------------------------
// Reduction: g_Mh[b][kp][d] = pack_f16x2(sum_p P[2kp][d], sum_p P[2kp+1][d]);
//            g_v = sum_p g_V
// ---------------------------------------------------------------------------
__global__ void __launch_bounds__(256)
kred()
{
    const int gid = blockIdx.x*blockDim.x + threadIdx.x;
    const int d4 = gid & 127;
    const int kp = (gid >> 7) & 255;
    const int b  = gid >> 15;

    const size_t pstride = (size_t)BATCH*DIM*DIM;
    const float* base = g_P + ((size_t)b*DIM + 2*kp)*DIM + 4*d4;
    float4 s0 = *(const float4*)(base);
    float4 s1 = *(const float4*)(base + DIM);
    #pragma unroll
    for (int p=1;p<SPLITS;p++){
        float4 t0 = *(const float4*)(base + p*pstride);
        float4 t1 = *(const float4*)(base + p*pstride + DIM);
        s0.x+=t0.x; s0.y+=t0.y; s0.z+=t0.z; s0.w+=t0.w;
        s1.x+=t1.x; s1.y+=t1.y; s1.z+=t1.z; s1.w+=t1.w;
    }
    uint4 u;
    u.x = pkh(s0.x, s1.x);
    u.y = pkh(s0.y, s1.y);
    u.z = pkh(s0.z, s1.z);
    u.w = pkh(s0.w, s1.w);
    ((uint4*)g_Mh)[((size_t)b*256 + kp)*128 + d4] = u;

    if (gid < BATCH*DIM/4){
        const float4* Vin = (const float4*)g_V;
        float4 s = Vin[gid];
        #pragma unroll
        for (int p=1;p<SPLITS;p++){
            float4 t = Vin[gid + p*(BATCH*DIM/4)];
            s.x+=t.x; s.y+=t.y; s.z+=t.z; s.w+=t.w;
        }
        ((float4*)g_v)[gid] = s;
    }
}

// ---------------------------------------------------------------------------
// Kernel 2: C[b,s,d] = sum_d' W[s,d'] * M[b,d',d] + bias[s]*v[b,d]
// 32x64 tiles, warp tile 16x16, 4-buffer ring, one barrier per 2 K-chunks.
// ---------------------------------------------------------------------------
__global__ void __launch_bounds__(256,4)
k2_proj(const float* __restrict__ Wm, const float* __restrict__ bias, float* __restrict__ out)
{
    __shared__ unsigned Ah[4][TM2][AR2];
    __shared__ unsigned Bh[4][8][BR2];

    const int tid  = threadIdx.x;
    const int lane = tid & 31;
    const int warp = tid >> 5;
    const int wm = warp & 1, wn = warp >> 1;
    const int tg = lane & 3;
    const int gp = lane >> 2;

    const int x  = blockIdx.x;
    const int nt = x & 7;
    const int mt = (x >> 3) & 15;
    const int b  = x >> 7;

    const bool ldA = (tid < 128);
    const int am  = tid >> 2;
    const int ak4 = tid & 3;
    const int pt  = tid - 128;
    const int bk  = pt >> 4;
    const int bn4 = pt & 15;

    const float* Wp = Wm + (size_t)(mt*TM2 + am)*DIM + 4*ak4;
    const unsigned* Mp = g_Mh + ((size_t)b*256 + bk)*512 + nt*TN2 + 4*bn4;

    float acc[2][4];
    #pragma unroll
    for (int j=0;j<2;j++)
        #pragma unroll
        for (int r=0;r<4;r++) acc[j][r]=0.f;

    float4 wq0, wq1; uint4 mq0, mq1;

    auto ldq = [&](int it, float4& wq, uint4& mq){
        if (ldA) wq = *(const float4*)(Wp + it*TK2);
        else     mq = *(const uint4*)(Mp + (size_t)it*8*512);
    };
    auto stq = [&](int buf, const float4& wq, const uint4& mq){
        if (ldA){
            Ah[buf][am][2*ak4]   = pkh(wq.x, wq.y);
            Ah[buf][am][2*ak4+1] = pkh(wq.z, wq.w);
        } else {
            *(uint4*)&Bh[buf][bk][4*bn4] = mq;
        }
    };
    auto do_mma = [&](int buf){
        unsigned a[4];
        const int mb = 16*wm + gp;
        a[0] = Ah[buf][mb][tg];
        a[1] = Ah[buf][mb+8][tg];
        a[2] = Ah[buf][mb][tg+4];
        a[3] = Ah[buf][mb+8][tg+4];
        const unsigned* Br0 = Bh[buf][tg];
        const unsigned* Br4 = Bh[buf][tg+4];
        #pragma unroll
        for (int j=0;j<2;j++){
            const int nb = 16*wn + 8*j + gp;
            unsigned b0 = Br0[nb];
            unsigned b1 = Br4[nb];
            mma_f16(acc[j], a, b0, b1);
        }
    };

    // prologue: buffers 0,1 <- chunks 0,1; q0,q1 <- chunks 2,3
    ldq(0, wq0, mq0); stq(0, wq0, mq0);
    ldq(1, wq1, mq1); stq(1, wq1, mq1);
    ldq(2, wq0, mq0); ldq(3, wq1, mq1);
    __syncthreads();

    #pragma unroll 1
    for (int it = 0; it < NIT2; it += 2){
        do_mma(it & 3);
        if (it + 2 < NIT2){
            stq((it+2)&3, wq0, mq0);
            stq((it+3)&3, wq1, mq1);
        }
        if (it + 4 < NIT2){
            ldq(it+4, wq0, mq0);
            ldq(it+5, wq1, mq1);
        }
        do_mma((it+1) & 3);
        __syncthreads();
    }

    float* Co = out + (((size_t)b)*DIM + mt*TM2)*DIM + nt*TN2;
    const int r0 = 16*wm + gp;
    const float b0s = bias[mt*TM2 + r0];
    const float b1s = bias[mt*TM2 + r0 + 8];
    #pragma unroll
    for (int j=0;j<2;j++){
        const int cc = 16*wn + 8*j + 2*tg;
        const float* vp = g_v + (size_t)b*DIM + nt*TN2 + cc;
        float v0 = vp[0], v1 = vp[1];
        *(float2*)&Co[(size_t)r0*DIM + cc] =
            make_float2(acc[j][0] + b0s*v0, acc[j][1] + b0s*v1);
        *(float2*)&Co[(size_t)(r0+8)*DIM + cc] =
            make_float2(acc[j][2] + b1s*v0, acc[j][3] + b1s*v1);
    }
}

extern "C" void kernel_launch(void* const* d_in, const int* in_sizes, int n_in,
                              void* d_out, int out_size)
{
    const float* H    = (const float*)d_in[0];   // hidden_states (4,8192,512)
    const float* E    = (const float*)d_in[1];   // positional_encodings (4,8192,512)
    const float* Wm   = (const float*)d_in[2];   // W (512,512)
    const float* bias = (const float*)d_in[3];   // b (512,)
    float* out = (float*)d_out;                  // (4,512,512)

    k1_outer<<<BATCH*4*4*SPLITS, 256>>>(H, E);
    kred<<<512, 256>>>();
    k2_proj<<<BATCH*16*8, 256>>>(Wm, bias, out);
}

// round 17
// speedup vs baseline: 1.0897x; 1.0273x over previous
#include <cuda_runtime.h>
#include <math.h>
#include <cstdint>

#define BATCH 4
#define SEQ   8192
#define DIM   512

// ---- Kernel 1: 128x128 tiles, K-split 4, fp16 m16n8k16, ldmatrix frags ----
#define TM    128
#define TN    128
#define TK    16              // K per chunk
#define SPLITS 4
#define KSPLIT (SEQ/SPLITS)
#define NITER (KSPLIT/TK)     // 128 chunks, 64 bodies
#define NBUF  4
#define AROWB 272             // bytes per k-row (128 f16 + 8 f16 pad)
#define CH_A  (16*AROWB)      // 4352 B per operand chunk
#define CH_B  (2*CH_A)        // 8704 B per chunk (A+B)

// ---- Kernel 2: 32x64 tiles, warp tile 16x16, 4-buffer / 2-chunk bodies ----
#define TM2   32
#define TN2   64
#define TK2   16
#define NIT2  (DIM/TK2)       // 32
#define AR2   12
#define BR2   72

__device__ float    g_P[(size_t)SPLITS*BATCH*DIM*DIM];   // 16 MB f32 split partials
__device__ unsigned g_Mh[(size_t)BATCH*(DIM/2)*DIM];     // 4 MB f16x2-packed M
__device__ float    g_V[SPLITS*BATCH*DIM];
__device__ float    g_v[BATCH*DIM];

__device__ __forceinline__ unsigned pkh(float lo, float hi){
    unsigned u; asm("cvt.rn.f16x2.f32 %0, %1, %2;" : "=r"(u) : "f"(hi), "f"(lo)); return u;
}
__device__ __forceinline__ void mma_f16(float c[4], const unsigned a[4], unsigned b0, unsigned b1){
    asm("mma.sync.aligned.m16n8k16.row.col.f32.f16.f16.f32 "
        "{%0,%1,%2,%3},{%4,%5,%6,%7},{%8,%9},{%0,%1,%2,%3};"
        : "+f"(c[0]), "+f"(c[1]), "+f"(c[2]), "+f"(c[3])
        : "r"(a[0]), "r"(a[1]), "r"(a[2]), "r"(a[3]), "r"(b0), "r"(b1));
}
__device__ __forceinline__ unsigned su32(const void* p){
    unsigned r;
    asm("{ .reg .u64 t; cvta.to.shared.u64 t, %1; cvt.u32.u64 %0, t; }" : "=r"(r) : "l"(p));
    return r;
}
#define LDSM4T(r, addr) \
    asm volatile("ldmatrix.sync.aligned.m8n8.x4.trans.shared.b16 {%0,%1,%2,%3}, [%4];" \
        : "=r"((r)[0]), "=r"((r)[1]), "=r"((r)[2]), "=r"((r)[3]) : "r"(addr))
#define STSV2(addr, u0, u1) \
    asm volatile("st.shared.v2.b32 [%0], {%1, %2};" :: "r"(addr), "r"(u0), "r"(u1))

// ---------------------------------------------------------------------------
// Kernel 1: g_P[split,b][m][n] = sum_t w_t H[t,m] E[t,n];  g_V (mt==0 CTAs)
// smem: plain f16 [k][feature] rows (272B stride); frags via ldmatrix.trans.
// 4-buffer ring, one __syncthreads per 2 chunks (K=32 body).  [R11 verbatim]
// ---------------------------------------------------------------------------
__global__ void __launch_bounds__(256,2)
k1_outer(const float* __restrict__ H, const float* __restrict__ E)
{
    __shared__ __align__(16) unsigned char sbuf[NBUF*CH_B];   // 34816 B
    __shared__ float vsm[256*4];

    const int tid  = threadIdx.x;
    const int lane = tid & 31;
    const int warp = tid >> 5;
    const int wm = warp & 3, wn = warp >> 2;   // warp tile 32m x 64n
    const int tg = lane & 3;
    const int gp = lane >> 2;

    const int x     = blockIdx.x;
    const int split = x & 3;
    const int nt    = (x >> 2) & 3;
    const int mt    = (x >> 4) & 3;
    const int b     = x >> 6;
    const int k0    = split * KSPLIT;

    const unsigned sb = su32(sbuf);

    // ---- consumer fragment lane offsets (bytes within chunk) ----
    const unsigned klA = (unsigned)((lane & 7) + ((lane >= 16) ? 8 : 0));
    const unsigned offA = klA*AROWB + (unsigned)(((lane >> 3) & 1) * 16) + (unsigned)(32*wm*2);
    const unsigned klB = (unsigned)((lane & 7) + (((lane >> 3) & 1) ? 8 : 0));
    const unsigned offB = klB*AROWB + (unsigned)((lane >= 16) ? 16 : 0) + (unsigned)(64*wn*2);

    // ---- producer coords ----
    const int kr = tid >> 5;   // k row 0..7 (also handles kr+8)
    const int c4 = tid & 31;   // float4 column
    const float* Ap = H + ((size_t)(b*SEQ + k0 + kr))*DIM + mt*TM + 4*c4;
    const float* Bp = E + ((size_t)(b*SEQ + k0 + kr))*DIM + nt*TN + 4*c4;
    const size_t step = (size_t)TK*DIM;

    const float lnalpha = logf((float)0.9996165783279395);
    const float c8f  = expf(-8.0f*lnalpha);    // w(k+8)/w(k)
    const float c16f = expf(-16.0f*lnalpha);
    float wt = expf((float)(SEQ-1 - (k0 + kr)) * lnalpha);

    float acc[2][8][4];
    #pragma unroll
    for (int i=0;i<2;i++)
        #pragma unroll
        for (int j=0;j<8;j++)
            #pragma unroll
            for (int r=0;r<4;r++) acc[i][j][r]=0.f;

    const bool dov = (mt == 0);
    float vacc[4] = {0.f,0.f,0.f,0.f};

    float4 q0[4], q1[4];     // [A row kr, A row kr+8, B row kr, B row kr+8]

    auto ldq = [&](int ck, float4* q){
        const float* ap = Ap + (size_t)ck*step;
        const float* bp = Bp + (size_t)ck*step;
        q[0] = *(const float4*)(ap);
        q[1] = *(const float4*)(ap + 8*DIM);
        q[2] = *(const float4*)(bp);
        q[3] = *(const float4*)(bp + 8*DIM);
    };
    auto stq = [&](int buf, const float4* q){
        unsigned base = sb + (unsigned)(buf*CH_B) + (unsigned)(kr*AROWB) + (unsigned)(c4*8);
        STSV2(base,           pkh(q[0].x,q[0].y), pkh(q[0].z,q[0].w));
        STSV2(base + 8*AROWB, pkh(q[1].x,q[1].y), pkh(q[1].z,q[1].w));
        const float w0 = wt, w1 = wt*c8f;
        float s0x=q[2].x*w0, s0y=q[2].y*w0, s0z=q[2].z*w0, s0w=q[2].w*w0;
        float s1x=q[3].x*w1, s1y=q[3].y*w1, s1z=q[3].z*w1, s1w=q[3].w*w1;
        if (dov){ vacc[0]+=s0x+s1x; vacc[1]+=s0y+s1y; vacc[2]+=s0z+s1z; vacc[3]+=s0w+s1w; }
        STSV2(base + CH_A,           pkh(s0x,s0y), pkh(s0z,s0w));
        STSV2(base + CH_A + 8*AROWB, pkh(s1x,s1y), pkh(s1z,s1w));
        wt *= c16f;
    };
    auto do_mma = [&](int buf){
        const unsigned Ab = sb + (unsigned)(buf*CH_B);
        const unsigned Bb = Ab + CH_A;
        unsigned a[2][4];
        LDSM4T(a[0], Ab + offA);
        LDSM4T(a[1], Ab + offA + 32);
        unsigned bf[4][4];
        #pragma unroll
        for (int jj=0;jj<4;jj++) LDSM4T(bf[jj], Bb + offB + (unsigned)(jj*32));
        #pragma unroll
        for (int i=0;i<2;i++){
            #pragma unroll
            for (int jj=0;jj<4;jj++){
                mma_f16(acc[i][2*jj],   a[i], bf[jj][0], bf[jj][1]);
                mma_f16(acc[i][2*jj+1], a[i], bf[jj][2], bf[jj][3]);
            }
        }
    };

    // prologue: buffers 0,1 <- chunks 0,1; q0,q1 <- chunks 2,3
    ldq(0, q0); ldq(1, q1);
    stq(0, q0); stq(1, q1);
    ldq(2, q0); ldq(3, q1);
    __syncthreads();

    #pragma unroll 1
    for (int it = 0; it < NITER; it += 2){
        if (it + 2 < NITER){
            stq((it+2)&3, q0);
            stq((it+3)&3, q1);
        }
        if (it + 4 < NITER){
            ldq(it+4, q0);
            ldq(it+5, q1);
        }
        do_mma(it & 3);
        do_mma((it+1) & 3);
        __syncthreads();
    }

    // write f32 partial tile
    float* Pp = g_P + (((size_t)(split*BATCH + b))*DIM + mt*TM)*DIM + nt*TN;
    #pragma unroll
    for (int i=0;i<2;i++){
        const int r = 32*wm + 16*i + gp;
        #pragma unroll
        for (int j=0;j<8;j++){
            const int cc = 64*wn + 8*j + 2*tg;
            *(float2*)&Pp[(size_t)r*DIM + cc]     = make_float2(acc[i][j][0], acc[i][j][1]);
            *(float2*)&Pp[(size_t)(r+8)*DIM + cc] = make_float2(acc[i][j][2], acc[i][j][3]);
        }
    }

    // v partial: reduce over kr groups
    if (dov){
        vsm[tid*4+0]=vacc[0]; vsm[tid*4+1]=vacc[1]; vsm[tid*4+2]=vacc[2]; vsm[tid*4+3]=vacc[3];
        __syncthreads();
        if (tid < 32){
            float s0=0.f,s1=0.f,s2=0.f,s3=0.f;
            #pragma unroll
            for (int r=0;r<8;r++){
                const float* p = vsm + ((r<<5) + tid)*4;
                s0+=p[0]; s1+=p[1]; s2+=p[2]; s3+=p[3];
            }
            float* vp = g_V + ((size_t)split*BATCH + b)*DIM + nt*TN + 4*tid;
            vp[0]=s0; vp[1]=s1; vp[2]=s2; vp[3]=s3;
        }
    }
}

// ---------------------------------------------------------------------------
// Reduction: g_Mh[b][kp][d] = pack_f16x2(sum_p P[2kp][d], sum_p P[2kp+1][d]);
//            g_v = sum_p g_V
// ---------------------------------------------------------------------------
__global__ void __launch_bounds__(256)
kred()
{
    const int gid = blockIdx.x*blockDim.x + threadIdx.x;
    const int d4 = gid & 127;
    const int kp = (gid >> 7) & 255;
    const int b  = gid >> 15;

    const size_t pstride = (size_t)BATCH*DIM*DIM;
    const float* base = g_P + ((size_t)b*DIM + 2*kp)*DIM + 4*d4;
    float4 s0 = *(const float4*)(base);
    float4 s1 = *(const float4*)(base + DIM);
    #pragma unroll
    for (int p=1;p<SPLITS;p++){
        float4 t0 = *(const float4*)(base + p*pstride);
        float4 t1 = *(const float4*)(base + p*pstride + DIM);
        s0.x+=t0.x; s0.y+=t0.y; s0.z+=t0.z; s0.w+=t0.w;
        s1.x+=t1.x; s1.y+=t1.y; s1.z+=t1.z; s1.w+=t1.w;
    }
    uint4 u;
    u.x = pkh(s0.x, s1.x);
    u.y = pkh(s0.y, s1.y);
    u.z = pkh(s0.z, s1.z);
    u.w = pkh(s0.w, s1.w);
    ((uint4*)g_Mh)[((size_t)b*256 + kp)*128 + d4] = u;

    if (gid < BATCH*DIM/4){
        const float4* Vin = (const float4*)g_V;
        float4 s = Vin[gid];
        #pragma unroll
        for (int p=1;p<SPLITS;p++){
            float4 t = Vin[gid + p*(BATCH*DIM/4)];
            s.x+=t.x; s.y+=t.y; s.z+=t.z; s.w+=t.w;
        }
        ((float4*)g_v)[gid] = s;
    }
}

// ---------------------------------------------------------------------------
// Kernel 2: C[b,s,d] = sum_d' W[s,d'] * M[b,d',d] + bias[s]*v[b,d]
// 32x64 tiles, warp tile 16x16, 4-buffer ring, one barrier per 2 K-chunks.
// ---------------------------------------------------------------------------
__global__ void __launch_bounds__(256,4)
k2_proj(const float* __restrict__ Wm, const float* __restrict__ bias, float* __restrict__ out)
{
    __shared__ unsigned Ah[4][TM2][AR2];
    __shared__ unsigned Bh[4][8][BR2];

    const int tid  = threadIdx.x;
    const int lane = tid & 31;
    const int warp = tid >> 5;
    const int wm = warp & 1, wn = warp >> 1;
    const int tg = lane & 3;
    const int gp = lane >> 2;

    const int x  = blockIdx.x;
    const int nt = x & 7;
    const int mt = (x >> 3) & 15;
    const int b  = x >> 7;

    const bool ldA = (tid < 128);
    const int am  = tid >> 2;
    const int ak4 = tid & 3;
    const int pt  = tid - 128;
    const int bk  = pt >> 4;
    const int bn4 = pt & 15;

    const float* Wp = Wm + (size_t)(mt*TM2 + am)*DIM + 4*ak4;
    const unsigned* Mp = g_Mh + ((size_t)b*256 + bk)*512 + nt*TN2 + 4*bn4;

    float acc[2][4];
    #pragma unroll
    for (int j=0;j<2;j++)
        #pragma unroll
        for (int r=0;r<4;r++) acc[j][r]=0.f;

    float4 wq0, wq1; uint4 mq0, mq1;

    auto ldq = [&](int it, float4& wq, uint4& mq){
        if (ldA) wq = *(const float4*)(Wp + it*TK2);
        else     mq = *(const uint4*)(Mp + (size_t)it*8*512);
    };
    auto stq = [&](int buf, const float4& wq, const uint4& mq){
        if (ldA){
            Ah[buf][am][2*ak4]   = pkh(wq.x, wq.y);
            Ah[buf][am][2*ak4+1] = pkh(wq.z, wq.w);
        } else {
            *(uint4*)&Bh[buf][bk][4*bn4] = mq;
        }
    };
    auto do_mma = [&](int buf){
        unsigned a[4];
        const int mb = 16*wm + gp;
        a[0] = Ah[buf][mb][tg];
        a[1] = Ah[buf][mb+8][tg];
        a[2] = Ah[buf][mb][tg+4];
        a[3] = Ah[buf][mb+8][tg+4];
        const unsigned* Br0 = Bh[buf][tg];
        const unsigned* Br4 = Bh[buf][tg+4];
        #pragma unroll
        for (int j=0;j<2;j++){
            const int nb = 16*wn + 8*j + gp;
            unsigned b0 = Br0[nb];
            unsigned b1 = Br4[nb];
            mma_f16(acc[j], a, b0, b1);
        }
    };

    // prologue: buffers 0,1 <- chunks 0,1; q regs <- chunks 2,3
    ldq(0, wq0, mq0); stq(0, wq0, mq0);
    ldq(1, wq1, mq1); stq(1, wq1, mq1);
    ldq(2, wq0, mq0); ldq(3, wq1, mq1);
    __syncthreads();

    #pragma unroll 1
    for (int it = 0; it < NIT2; it += 2){
        do_mma(it & 3);
        if (it + 2 < NIT2){
            stq((it+2)&3, wq0, mq0);
            stq((it+3)&3, wq1, mq1);
        }
        if (it + 4 < NIT2){
            ldq(it+4, wq0, mq0);
            ldq(it+5, wq1, mq1);
        }
        do_mma((it+1) & 3);
        __syncthreads();
    }

    float* Co = out + (((size_t)b)*DIM + mt*TM2)*DIM + nt*TN2;
    const int r0 = 16*wm + gp;
    const float b0s = bias[mt*TM2 + r0];
    const float b1s = bias[mt*TM2 + r0 + 8];
    #pragma unroll
    for (int j=0;j<2;j++){
        const int cc = 16*wn + 8*j + 2*tg;
        const float* vp = g_v + (size_t)b*DIM + nt*TN2 + cc;
        float v0 = vp[0], v1 = vp[1];
        *(float2*)&Co[(size_t)r0*DIM + cc] =
            make_float2(acc[j][0] + b0s*v0, acc[j][1] + b0s*v1);
        *(float2*)&Co[(size_t)(r0+8)*DIM + cc] =
            make_float2(acc[j][2] + b1s*v0, acc[j][3] + b1s*v1);
    }
}

extern "C" void kernel_launch(void* const* d_in, const int* in_sizes, int n_in,
                              void* d_out, int out_size)
{
    const float* H    = (const float*)d_in[0];   // hidden_states (4,8192,512)
    const float* E    = (const float*)d_in[1];   // positional_encodings (4,8192,512)
    const float* Wm   = (const float*)d_in[2];   // W (512,512)
    const float* bias = (const float*)d_in[3];   // b (512,)
    float* out = (float*)d_out;                  // (4,512,512)

    k1_outer<<<BATCH*4*4*SPLITS, 256>>>(H, E);
    kred<<<512, 256>>>();
    k2_proj<<<BATCH*16*8, 256>>>(Wm, bias, out);
}